// round 2
// baseline (speedup 1.0000x reference)
#include <cuda_runtime.h>
#include <cstdint>

#define HH 512
#define WW 512
#define WORDS 16                  // uint32 words per image row
#define SLAB 128                  // a-rows per block
#define HALO 3                    // max row offset
#define NTH 512                   // threads per block
#define NWARPS (NTH / 32)
#define NOFF 12
#define NB 128                    // batch

// global partial counters: [image][offset][2] = {diff, n11}; zero-init at load,
// reset by finalize kernel after each use -> deterministic across graph replays.
__device__ int g_cnt[NB * NOFF * 2];

__global__ __launch_bounds__(NTH, 4)
void glcm_count(const float* __restrict__ in)
{
    constexpr int RS[NOFF] = {0, 1, 1, 1, 0, 2, 2, 2, 0, 3, 3, 3};
    constexpr int CS[NOFF] = {1, 1, 0, -1, 2, 2, 0, -2, 3, 3, 0, -3};

    __shared__ unsigned int sm[(SLAB + HALO) * WORDS + 16];
    __shared__ int s_diff[NOFF];
    __shared__ int s_n11[NOFF];

    const int tid  = threadIdx.x;
    const int lane = tid & 31;
    const int warp = tid >> 5;
    const int r0   = blockIdx.x * SLAB;      // first a-row of this slab
    const int b    = blockIdx.y;             // image

    if (tid < NOFF) { s_diff[tid] = 0; s_n11[tid] = 0; }

    // ---------------- pack sign bits for rows [r0, r0+nload) -----------------
    const int nload = min(SLAB + HALO, HH - r0);
    if (tid == 0) sm[nload * WORDS] = 0u;    // pad word (masked reads only)

    const float4* img4 = reinterpret_cast<const float4*>(
        in + ((size_t)b * HH + r0) * WW);
    const int NG = nload * 4;                // groups of 128 floats

    #pragma unroll 4
    for (int g = warp; g < NG; g += NWARPS) {
        float4 v = img4[g * 32 + lane];
        unsigned nib = (v.x > 0.0f ? 1u : 0u)
                     | (v.y > 0.0f ? 2u : 0u)
                     | (v.z > 0.0f ? 4u : 0u)
                     | (v.w > 0.0f ? 8u : 0u);
        unsigned pack = nib << ((lane & 7) * 4);
        pack |= __shfl_xor_sync(0xffffffffu, pack, 1);
        pack |= __shfl_xor_sync(0xffffffffu, pack, 2);
        pack |= __shfl_xor_sync(0xffffffffu, pack, 4);
        if ((lane & 7) == 0) sm[g * 4 + (lane >> 3)] = pack;
    }
    __syncthreads();

    // ---------------- popcount sweep, 12 offsets -----------------------------
    #pragma unroll
    for (int off = 0; off < NOFF; ++off) {
        const int R = RS[off];
        const int C = CS[off];
        const int nrows = min(SLAB, HH - R - r0);   // a-rows owned by this slab
        const int total = nrows * WORDS;

        unsigned diff = 0, n11 = 0;
        for (int i = tid; i < total; i += NTH) {
            const int w = i & (WORDS - 1);
            const unsigned A = sm[i];
            const int bi = i + R * WORDS;
            unsigned B;
            if (C > 0)       B = __funnelshift_r(sm[bi], sm[bi + 1], C);
            else if (C < 0)  B = __funnelshift_l(sm[bi - 1], sm[bi], -C);
            else             B = sm[bi];

            unsigned m = 0xffffffffu;
            if (C > 0 && w == WORDS - 1) m = 0xffffffffu >> C;
            if (C < 0 && w == 0)         m = 0xffffffffu << (-C);

            diff += __popc((A ^ B) & m);
            n11  += __popc((A & B) & m);
        }
        diff = __reduce_add_sync(0xffffffffu, diff);
        n11  = __reduce_add_sync(0xffffffffu, n11);
        if (lane == 0) {
            atomicAdd(&s_diff[off], (int)diff);
            atomicAdd(&s_n11[off], (int)n11);
        }
    }
    __syncthreads();

    if (tid < NOFF) {
        atomicAdd(&g_cnt[(b * NOFF + tid) * 2 + 0], s_diff[tid]);
        atomicAdd(&g_cnt[(b * NOFF + tid) * 2 + 1], s_n11[tid]);
    }
}

__global__ void glcm_finalize(float* __restrict__ out)
{
    constexpr int RS[NOFF] = {0, 1, 1, 1, 0, 2, 2, 2, 0, 3, 3, 3};
    constexpr int CS[NOFF] = {1, 1, 0, -1, 2, 2, 0, -2, 3, 3, 0, -3};

    const int idx = blockIdx.x * blockDim.x + threadIdx.x;
    if (idx >= NB * NOFF) return;
    const int b   = idx / NOFF;
    const int off = idx % NOFF;

    const int diff = g_cnt[idx * 2 + 0];
    const int n11  = g_cnt[idx * 2 + 1];
    g_cnt[idx * 2 + 0] = 0;                 // reset for next replay
    g_cnt[idx * 2 + 1] = 0;

    const int R  = RS[off];
    const int Ca = CS[off] < 0 ? -CS[off] : CS[off];
    const int N  = (HH - R) * (WW - Ca);
    const int n00 = N - n11 - diff;

    const float inv = 1.0f / (float)(2 * N - 4 * n00);
    float* o = out + (size_t)b * (NOFF * 4) + off * 4;
    o[0] = (float)(4 * n00) * inv;
    const float v1 = (float)(2 * diff - 4 * n00) * inv;
    o[1] = v1;
    o[2] = v1;
    o[3] = (float)(2 * (N - 2 * diff)) * inv;
}

extern "C" void kernel_launch(void* const* d_in, const int* in_sizes, int n_in,
                              void* d_out, int out_size)
{
    (void)n_in; (void)out_size; (void)in_sizes;
    const float* in = (const float*)d_in[0];
    float* out = (float*)d_out;

    dim3 grid(HH / SLAB, NB);               // 4 x 128 = 512 blocks
    glcm_count<<<grid, NTH>>>(in);
    glcm_finalize<<<(NB * NOFF + 255) / 256, 256>>>(out);
}